// round 8
// baseline (speedup 1.0000x reference)
#include <cuda_runtime.h>
#include <cuda_bf16.h>
#include <stdint.h>
#include <math.h>

// Problem constants
#define D_MODEL 1024
#define NHEAD   16
#define DH      64
#define SEQ     2048
#define BATCH   4
#define MTOT    (BATCH*SEQ)          // 8192
#define KE      2048                 // split storage: [hi(1024) | lo(1024)]

// ---------------------------------------------------------------------------
// Scratch (device globals; no allocation anywhere)
// ---------------------------------------------------------------------------
__device__ float g_Q[BATCH*NHEAD*SEQ*DH];   // [B,H,S,Dh] fp32
__device__ float g_K[BATCH*NHEAD*SEQ*DH];
__device__ float g_V[BATCH*NHEAD*SEQ*DH];
__device__ float g_T[MTOT*D_MODEL];         // attention output, [B,S,H*Dh] fp32

__device__ __nv_bfloat16 g_Xext[(size_t)MTOT*KE];       // X split hi|lo
__device__ __nv_bfloat16 g_Wext[4][(size_t)D_MODEL*KE]; // WQ,WK,WV,WO split
__device__ __nv_bfloat16 g_Text[(size_t)MTOT*KE];       // attn-out split

// ---------------------------------------------------------------------------
// Helpers (portable PTX only: cp.async, ldmatrix, mma.sync — all sm_80+)
// ---------------------------------------------------------------------------
__device__ __forceinline__ uint32_t smem_u32(const void* p) {
    uint32_t a;
    asm("{ .reg .u64 t; cvta.to.shared.u64 t, %1; cvt.u32.u64 %0, t; }" : "=r"(a) : "l"(p));
    return a;
}
__device__ __forceinline__ void cp16(uint32_t saddr, const void* gaddr) {
    asm volatile("cp.async.cg.shared.global [%0], [%1], 16;" :: "r"(saddr), "l"(gaddr));
}
__device__ __forceinline__ void ldsm_x4(uint32_t& r0, uint32_t& r1, uint32_t& r2, uint32_t& r3, uint32_t addr) {
    asm volatile("ldmatrix.sync.aligned.m8n8.x4.shared.b16 {%0,%1,%2,%3}, [%4];"
                 : "=r"(r0), "=r"(r1), "=r"(r2), "=r"(r3) : "r"(addr));
}
__device__ __forceinline__ void mma_bf16(float& c0, float& c1, float& c2, float& c3,
                                         uint32_t a0, uint32_t a1, uint32_t a2, uint32_t a3,
                                         uint32_t b0, uint32_t b1) {
    asm volatile("mma.sync.aligned.m16n8k16.row.col.f32.bf16.bf16.f32 "
                 "{%0,%1,%2,%3}, {%4,%5,%6,%7}, {%8,%9}, {%0,%1,%2,%3};"
                 : "+f"(c0), "+f"(c1), "+f"(c2), "+f"(c3)
                 : "r"(a0), "r"(a1), "r"(a2), "r"(a3), "r"(b0), "r"(b1));
}
#define SWZ(x) ((x) ^ (((x) >> 3) & 0x70))

// ---------------------------------------------------------------------------
// fp32 -> bf16 split (hi|lo) converter.
// mode 0..3: weights -> g_Wext[mode];  mode 4: X -> g_Xext;  mode 5: g_T -> g_Text
// ---------------------------------------------------------------------------
__global__ void convert_split(const float* __restrict__ src, int n, int mode)
{
    __nv_bfloat16* dst = (mode < 4) ? g_Wext[mode] : (mode == 4 ? g_Xext : g_Text);
    const float* s = (mode == 5) ? g_T : src;
    for (int i = blockIdx.x * blockDim.x + threadIdx.x; i < n; i += gridDim.x * blockDim.x) {
        int r = i >> 10, c = i & 1023;
        float x = s[i];
        __nv_bfloat16 hi = __float2bfloat16(x);
        float lo = x - __bfloat162float(hi);
        dst[(size_t)r * KE + c]        = hi;
        dst[(size_t)r * KE + 1024 + c] = __float2bfloat16(lo);
    }
}

// ---------------------------------------------------------------------------
// bf16 tensor-core GEMM (mma.sync) with hi/lo compensation.
// C[m,n] = sum_k A[m,k]*W[n,k] via 3 bf16 term passes: (Ah,Wh),(Ah,Wl),(Al,Wh)
// = 48 K-chunks of 64, accumulated in fp32 registers.
// Block tile M=128, N=128, BK=64. 256 threads = 8 warps (4m x 2n), warp 32x64.
// Double-buffered cp.async; SW128-swizzled smem; ldmatrix.x4 operand loads.
// mode 0/1/2: A=g_Xext, W=g_Wext[mode], dst=g_Q/K/V in [B,H,S,Dh]
// mode 3:     A=g_Text, W=g_Wext[3],    dst=outp row-major [8192,1024]
// ---------------------------------------------------------------------------
#define TILE_BYTES 16384            // 128 rows x 128B (64 bf16)
#define GSM_BYTES  (4 * TILE_BYTES) // A0,B0,A1,B1

__global__ __launch_bounds__(256) void gemm_mma(float* __restrict__ outp, int mode)
{
    extern __shared__ char smem[];
    uint32_t sb = smem_u32(smem);
    const uint32_t aS[2] = {sb,                  sb + 2 * TILE_BYTES};
    const uint32_t bS[2] = {sb + TILE_BYTES,     sb + 3 * TILE_BYTES};

    int tid = threadIdx.x;
    int wid = tid >> 5;
    int lid = tid & 31;
    int wm = wid >> 1;              // 0..3  (32 rows each)
    int wn = wid & 1;               // 0..1  (64 cols each)
    int m0 = blockIdx.y * 128;
    int n0 = blockIdx.x * 128;

    const __nv_bfloat16* A = (mode == 3) ? g_Text : g_Xext;
    const __nv_bfloat16* W = g_Wext[mode];
    const char* Abase = (const char*)(A + (size_t)m0 * KE);
    const char* Wbase = (const char*)(W + (size_t)n0 * KE);

    float acc[2][8][4];
#pragma unroll
    for (int mt = 0; mt < 2; ++mt)
#pragma unroll
        for (int j = 0; j < 8; ++j)
#pragma unroll
            for (int v = 0; v < 4; ++v) acc[mt][j][v] = 0.f;

    // Per-thread loader coords (4 segs of 16B per matrix per chunk)
    int lrow[4], lcol[4];
    uint32_t lso[4];
#pragma unroll
    for (int t = 0; t < 4; ++t) {
        int idx = tid + t * 256;
        lrow[t] = idx >> 3;
        lcol[t] = (idx & 7) * 16;
        lso[t]  = SWZ((uint32_t)(lrow[t] * 128 + lcol[t]));
    }

    // chunk i (0..47): term = i>>4, c = i&15
    // ka = (term==2 ? 1024 : 0) + c*64 ; kb = (term==1 ? 1024 : 0) + c*64  (elements)
    {
        // prefetch chunk 0 (ka = kb = 0)
#pragma unroll
        for (int t = 0; t < 4; ++t) {
            size_t g = (size_t)lrow[t] * 4096 + lcol[t];
            cp16(aS[0] + lso[t], Abase + g);
            cp16(bS[0] + lso[t], Wbase + g);
        }
        asm volatile("cp.async.commit_group;" ::: "memory");
    }

    for (int i = 0; i < 48; ++i) {
        int cur = i & 1;
        if (i + 1 < 48) {
            int j = i + 1, tterm = j >> 4, c = j & 15;
            int ka = ((tterm == 2) ? 1024 : 0) + c * 64;
            int kb = ((tterm == 1) ? 1024 : 0) + c * 64;
            const char* ag = Abase + (size_t)ka * 2;
            const char* bg = Wbase + (size_t)kb * 2;
#pragma unroll
            for (int t = 0; t < 4; ++t) {
                size_t g = (size_t)lrow[t] * 4096 + lcol[t];
                cp16(aS[cur ^ 1] + lso[t], ag + g);
                cp16(bS[cur ^ 1] + lso[t], bg + g);
            }
            asm volatile("cp.async.commit_group;" ::: "memory");
            asm volatile("cp.async.wait_group 1;" ::: "memory");
        } else {
            asm volatile("cp.async.wait_group 0;" ::: "memory");
        }
        __syncthreads();

        // Compute on buffer `cur`: 4 k16 steps
#pragma unroll
        for (int ks = 0; ks < 4; ++ks) {
            int kb2 = ks * 32;   // byte offset within 128B row
            uint32_t a[2][4];
#pragma unroll
            for (int mt = 0; mt < 2; ++mt) {
                int row = wm * 32 + mt * 16 + (lid & 15);
                uint32_t addr = aS[cur] + SWZ((uint32_t)(row * 128 + kb2 + ((lid >> 4) * 16)));
                ldsm_x4(a[mt][0], a[mt][1], a[mt][2], a[mt][3], addr);
            }
            uint32_t b[4][4];
#pragma unroll
            for (int ng = 0; ng < 4; ++ng) {
                int row = wn * 64 + ng * 16 + ((lid >> 4) << 3) + (lid & 7);
                uint32_t addr = bS[cur] + SWZ((uint32_t)(row * 128 + kb2 + (((lid >> 3) & 1) * 16)));
                ldsm_x4(b[ng][0], b[ng][1], b[ng][2], b[ng][3], addr);
            }
#pragma unroll
            for (int mt = 0; mt < 2; ++mt)
#pragma unroll
                for (int ng = 0; ng < 4; ++ng) {
                    mma_bf16(acc[mt][ng*2+0][0], acc[mt][ng*2+0][1], acc[mt][ng*2+0][2], acc[mt][ng*2+0][3],
                             a[mt][0], a[mt][1], a[mt][2], a[mt][3], b[ng][0], b[ng][1]);
                    mma_bf16(acc[mt][ng*2+1][0], acc[mt][ng*2+1][1], acc[mt][ng*2+1][2], acc[mt][ng*2+1][3],
                             a[mt][0], a[mt][1], a[mt][2], a[mt][3], b[ng][2], b[ng][3]);
                }
        }
        __syncthreads();
    }

    // Epilogue: lane (row r = lane>>2 [+8], cols 2*(lane&3)+{0,1})
#pragma unroll
    for (int mt = 0; mt < 2; ++mt) {
#pragma unroll
        for (int j = 0; j < 8; ++j) {
            int row = m0 + wm * 32 + mt * 16 + (lid >> 2);
            int col = n0 + wn * 64 + j * 8 + ((lid & 3) << 1);
            float2 v0 = make_float2(acc[mt][j][0], acc[mt][j][1]);
            float2 v1 = make_float2(acc[mt][j][2], acc[mt][j][3]);
            if (mode == 3) {
                *(float2*)(outp + (size_t)row * D_MODEL + col)       = v0;
                *(float2*)(outp + (size_t)(row + 8) * D_MODEL + col) = v1;
            } else {
                float* base = (mode == 0) ? g_Q : (mode == 1) ? g_K : g_V;
                int h = col >> 6, d0 = col & 63;
                int b0_ = row >> 11, s0 = row & 2047;
                int r1 = row + 8;
                int b1_ = r1 >> 11, s1 = r1 & 2047;
                *(float2*)(base + (((size_t)(b0_ * NHEAD + h)) * SEQ + s0) * DH + d0) = v0;
                *(float2*)(base + (((size_t)(b1_ * NHEAD + h)) * SEQ + s1) * DH + d0) = v1;
            }
        }
    }
}

// ---------------------------------------------------------------------------
// Flash attention, fp32, causal (unchanged; known-good from R1).
// ---------------------------------------------------------------------------
#define APAD 68
#define ASMEM_BYTES (4 * 64 * APAD * 4)

__global__ __launch_bounds__(256) void attn_kernel()
{
    extern __shared__ float sm[];
    float* Qst = sm;
    float* Kst = sm + 64 * APAD;
    float* Vs  = sm + 2 * 64 * APAD;
    float* Pst = sm + 3 * 64 * APAD;

    int tid = threadIdx.x;
    int tx  = tid & 15;
    int ty  = tid >> 4;
    int qt  = blockIdx.x;
    int bh  = blockIdx.y;

    const float* Qb = g_Q + ((size_t)bh * SEQ + qt * 64) * DH;

#pragma unroll
    for (int r = 0; r < 4; ++r) {
        int row = r * 16 + ty;
        int c4  = tx * 4;
        float4 v = *(const float4*)(Qb + row * DH + c4);
        Qst[(c4 + 0) * APAD + row] = v.x;
        Qst[(c4 + 1) * APAD + row] = v.y;
        Qst[(c4 + 2) * APAD + row] = v.z;
        Qst[(c4 + 3) * APAD + row] = v.w;
    }

    float o[4][4];
    float mrow[4], lrow[4];
#pragma unroll
    for (int i = 0; i < 4; ++i) {
        mrow[i] = -1e30f; lrow[i] = 0.f;
#pragma unroll
        for (int j = 0; j < 4; ++j) o[i][j] = 0.f;
    }

    const float scale = 0.125f;

    for (int kt = 0; kt <= qt; ++kt) {
        const float* Kb = g_K + ((size_t)bh * SEQ + kt * 64) * DH;
        const float* Vb = g_V + ((size_t)bh * SEQ + kt * 64) * DH;
#pragma unroll
        for (int r = 0; r < 4; ++r) {
            int row = r * 16 + ty;
            int c4  = tx * 4;
            float4 kv = *(const float4*)(Kb + row * DH + c4);
            Kst[(c4 + 0) * APAD + row] = kv.x;
            Kst[(c4 + 1) * APAD + row] = kv.y;
            Kst[(c4 + 2) * APAD + row] = kv.z;
            Kst[(c4 + 3) * APAD + row] = kv.w;
            float4 vv = *(const float4*)(Vb + row * DH + c4);
            *(float4*)&Vs[row * APAD + c4] = vv;
        }
        __syncthreads();

        float s[4][4];
#pragma unroll
        for (int i = 0; i < 4; ++i)
#pragma unroll
            for (int j = 0; j < 4; ++j) s[i][j] = 0.f;

#pragma unroll 8
        for (int d = 0; d < 64; ++d) {
            float4 qv = *(const float4*)&Qst[d * APAD + ty * 4];
            float4 kv = *(const float4*)&Kst[d * APAD + tx * 4];
            float qa[4] = {qv.x, qv.y, qv.z, qv.w};
            float ka[4] = {kv.x, kv.y, kv.z, kv.w};
#pragma unroll
            for (int i = 0; i < 4; ++i)
#pragma unroll
                for (int j = 0; j < 4; ++j)
                    s[i][j] = fmaf(qa[i], ka[j], s[i][j]);
        }

        if (kt == qt) {
#pragma unroll
            for (int i = 0; i < 4; ++i)
#pragma unroll
                for (int j = 0; j < 4; ++j)
                    s[i][j] = ((tx * 4 + j) > (ty * 4 + i)) ? -1e30f : s[i][j] * scale;
        } else {
#pragma unroll
            for (int i = 0; i < 4; ++i)
#pragma unroll
                for (int j = 0; j < 4; ++j) s[i][j] *= scale;
        }

        float p[4][4];
#pragma unroll
        for (int i = 0; i < 4; ++i) {
            float mt = s[i][0];
            mt = fmaxf(mt, s[i][1]); mt = fmaxf(mt, s[i][2]); mt = fmaxf(mt, s[i][3]);
#pragma unroll
            for (int off = 8; off >= 1; off >>= 1)
                mt = fmaxf(mt, __shfl_xor_sync(0xffffffffu, mt, off, 16));
            float mnew = fmaxf(mrow[i], mt);
            float alpha = __expf(mrow[i] - mnew);
            float lt = 0.f;
#pragma unroll
            for (int j = 0; j < 4; ++j) {
                p[i][j] = __expf(s[i][j] - mnew);
                lt += p[i][j];
            }
#pragma unroll
            for (int off = 8; off >= 1; off >>= 1)
                lt += __shfl_xor_sync(0xffffffffu, lt, off, 16);
            lrow[i] = lrow[i] * alpha + lt;
            mrow[i] = mnew;
#pragma unroll
            for (int j = 0; j < 4; ++j) o[i][j] *= alpha;
        }

#pragma unroll
        for (int i = 0; i < 4; ++i)
#pragma unroll
            for (int j = 0; j < 4; ++j)
                Pst[(tx * 4 + j) * APAD + ty * 4 + i] = p[i][j];
        __syncthreads();

#pragma unroll 8
        for (int k = 0; k < 64; ++k) {
            float4 pv = *(const float4*)&Pst[k * APAD + ty * 4];
            float4 vv = *(const float4*)&Vs[k * APAD + tx * 4];
            float pa[4] = {pv.x, pv.y, pv.z, pv.w};
            float va[4] = {vv.x, vv.y, vv.z, vv.w};
#pragma unroll
            for (int i = 0; i < 4; ++i)
#pragma unroll
                for (int j = 0; j < 4; ++j)
                    o[i][j] = fmaf(pa[i], va[j], o[i][j]);
        }
        __syncthreads();
    }

    int b = bh >> 4;
    int h = bh & 15;
#pragma unroll
    for (int i = 0; i < 4; ++i) {
        float inv = 1.f / lrow[i];
        int q = qt * 64 + ty * 4 + i;
        float4 v = make_float4(o[i][0] * inv, o[i][1] * inv, o[i][2] * inv, o[i][3] * inv);
        *(float4*)&g_T[((size_t)(b * SEQ + q)) * D_MODEL + h * 64 + tx * 4] = v;
    }
}

// ---------------------------------------------------------------------------
// Launch
// ---------------------------------------------------------------------------
extern "C" void kernel_launch(void* const* d_in, const int* in_sizes, int n_in,
                              void* d_out, int out_size)
{
    const float* X  = (const float*)d_in[0];
    const float* WQ = (const float*)d_in[1];
    const float* WK = (const float*)d_in[2];
    const float* WV = (const float*)d_in[3];
    const float* WO = (const float*)d_in[4];
    float* out = (float*)d_out;

    // fp32 -> bf16 hi/lo splits
    convert_split<<<2048, 256>>>(X,  MTOT * D_MODEL, 4);
    convert_split<<<1024, 256>>>(WQ, D_MODEL * D_MODEL, 0);
    convert_split<<<1024, 256>>>(WK, D_MODEL * D_MODEL, 1);
    convert_split<<<1024, 256>>>(WV, D_MODEL * D_MODEL, 2);
    convert_split<<<1024, 256>>>(WO, D_MODEL * D_MODEL, 3);

    cudaFuncSetAttribute(gemm_mma, cudaFuncAttributeMaxDynamicSharedMemorySize, GSM_BYTES);
    dim3 ggrid(D_MODEL / 128, MTOT / 128);   // (8, 64)
    gemm_mma<<<ggrid, 256, GSM_BYTES>>>(nullptr, 0);   // Q
    gemm_mma<<<ggrid, 256, GSM_BYTES>>>(nullptr, 1);   // K
    gemm_mma<<<ggrid, 256, GSM_BYTES>>>(nullptr, 2);   // V

    cudaFuncSetAttribute(attn_kernel, cudaFuncAttributeMaxDynamicSharedMemorySize, ASMEM_BYTES);
    dim3 agrid(SEQ / 64, BATCH * NHEAD);     // (32, 64)
    attn_kernel<<<agrid, 256, ASMEM_BYTES>>>();

    convert_split<<<2048, 256>>>(X /*unused*/, MTOT * D_MODEL, 5);  // g_T -> g_Text
    gemm_mma<<<ggrid, 256, GSM_BYTES>>>(out, 3);       // output projection
}

// round 9
// speedup vs baseline: 4.6970x; 4.6970x over previous
#include <cuda_runtime.h>
#include <cuda_fp16.h>
#include <stdint.h>

#define D_MODEL 1024
#define NHEAD   16
#define DH      64
#define SEQ     2048
#define BATCH   4
#define MTOT    8192
#define KE      2048

// ---------------- scratch globals (no allocation) ----------------
__device__ __half g_Xe[(size_t)MTOT*KE];                 // X hi|lo
__device__ __half g_Te[(size_t)MTOT*KE];                 // attn out hi|lo
__device__ __half g_W[4][(size_t)D_MODEL*D_MODEL];       // weights fp16
__device__ __half g_Qh[(size_t)BATCH*NHEAD*SEQ*DH];      // [B,H,S,64]
__device__ __half g_Kh[(size_t)BATCH*NHEAD*SEQ*DH];
__device__ __half g_Vh[(size_t)BATCH*NHEAD*SEQ*DH];

// ---------------- helpers ----------------
__device__ __forceinline__ uint32_t smem_u32(const void* p) {
    uint32_t a;
    asm("{ .reg .u64 t; cvta.to.shared.u64 t, %1; cvt.u32.u64 %0, t; }" : "=r"(a) : "l"(p));
    return a;
}
__device__ __forceinline__ void cp16(uint32_t s, const void* g) {
    asm volatile("cp.async.cg.shared.global [%0], [%1], 16;" :: "r"(s), "l"(g));
}
#define CP_COMMIT() asm volatile("cp.async.commit_group;" ::: "memory")
#define CP_WAIT(n)  asm volatile("cp.async.wait_group %0;" :: "n"(n) : "memory")

__device__ __forceinline__ void ldsm(uint32_t& r0, uint32_t& r1, uint32_t& r2, uint32_t& r3, uint32_t a) {
    asm volatile("ldmatrix.sync.aligned.m8n8.x4.shared.b16 {%0,%1,%2,%3}, [%4];"
                 : "=r"(r0), "=r"(r1), "=r"(r2), "=r"(r3) : "r"(a));
}
__device__ __forceinline__ void ldsmT(uint32_t& r0, uint32_t& r1, uint32_t& r2, uint32_t& r3, uint32_t a) {
    asm volatile("ldmatrix.sync.aligned.m8n8.x4.trans.shared.b16 {%0,%1,%2,%3}, [%4];"
                 : "=r"(r0), "=r"(r1), "=r"(r2), "=r"(r3) : "r"(a));
}
__device__ __forceinline__ void mma16(float* c, uint32_t a0, uint32_t a1, uint32_t a2, uint32_t a3,
                                      uint32_t b0, uint32_t b1) {
    asm volatile("mma.sync.aligned.m16n8k16.row.col.f32.f16.f16.f32 "
                 "{%0,%1,%2,%3}, {%4,%5,%6,%7}, {%8,%9}, {%0,%1,%2,%3};"
                 : "+f"(c[0]), "+f"(c[1]), "+f"(c[2]), "+f"(c[3])
                 : "r"(a0), "r"(a1), "r"(a2), "r"(a3), "r"(b0), "r"(b1));
}
#define SWZ(x) ((uint32_t)(x) ^ ((((uint32_t)(x)) >> 3) & 0x70))

__device__ __forceinline__ uint32_t packh2(float a, float b) {
    __half2 h = __floats2half2_rn(a, b);
    return *reinterpret_cast<uint32_t*>(&h);
}

// ---------------- converters ----------------
__global__ void conv_x(const float* __restrict__ s) {
    for (int i = blockIdx.x * blockDim.x + threadIdx.x; i < MTOT * D_MODEL; i += gridDim.x * blockDim.x) {
        int r = i >> 10, c = i & 1023;
        float x = s[i];
        __half h = __float2half_rn(x);
        g_Xe[(size_t)r * KE + c]        = h;
        g_Xe[(size_t)r * KE + 1024 + c] = __float2half_rn(x - __half2float(h));
    }
}
__global__ void conv_w(const float* __restrict__ s, int m) {
    for (int i = blockIdx.x * blockDim.x + threadIdx.x; i < D_MODEL * D_MODEL; i += gridDim.x * blockDim.x)
        g_W[m][i] = __float2half_rn(s[i]);
}

// ---------------- 2-pass fp16 GEMM: C = (Ah+Al) * W^T ----------------
// 128x128 tile, 16 K-chunks of 64; stage = Ah|Al|B (48KB), double buffered.
#define GST 49152
__global__ __launch_bounds__(256) void gemm_h(float* __restrict__ outp, int mode)
{
    extern __shared__ char smem[];
    uint32_t sb = smem_u32(smem);
    int tid = threadIdx.x, lid = tid & 31, wid = tid >> 5;
    int wm = wid >> 1, wn = wid & 1;
    int m0 = blockIdx.y * 128, n0 = blockIdx.x * 128;

    const __half* A = (mode == 3) ? g_Te : g_Xe;
    const char* Ab = (const char*)(A + (size_t)m0 * KE);
    const char* Bb = (const char*)(g_W[mode] + (size_t)n0 * D_MODEL);

    float acc[2][8][4];
#pragma unroll
    for (int a = 0; a < 2; ++a)
#pragma unroll
        for (int j = 0; j < 8; ++j)
#pragma unroll
            for (int v = 0; v < 4; ++v) acc[a][j][v] = 0.f;

    auto LD = [&](int c, uint32_t st) {
#pragma unroll
        for (int t = 0; t < 4; ++t) {
            int idx = tid + t * 256, row = idx >> 3, cc = (idx & 7) * 16;
            uint32_t so = SWZ(row * 128 + cc);
            cp16(st + so,         Ab + (size_t)row * 4096 + c * 128 + cc);
            cp16(st + 16384 + so, Ab + (size_t)row * 4096 + 2048 + c * 128 + cc);
            cp16(st + 32768 + so, Bb + (size_t)row * 2048 + c * 128 + cc);
        }
    };

    LD(0, sb); CP_COMMIT();
    for (int i = 0; i < 16; ++i) {
        int cur = i & 1;
        if (i + 1 < 16) { LD(i + 1, sb + (cur ^ 1) * GST); CP_COMMIT(); CP_WAIT(1); }
        else CP_WAIT(0);
        __syncthreads();
        uint32_t st = sb + cur * GST;
#pragma unroll
        for (int ks = 0; ks < 4; ++ks) {
            int kb = ks * 32;
            uint32_t ah[2][4], al[2][4];
#pragma unroll
            for (int mt = 0; mt < 2; ++mt) {
                uint32_t off = SWZ((wm * 32 + mt * 16 + (lid & 15)) * 128 + kb + (lid >> 4) * 16);
                ldsm(ah[mt][0], ah[mt][1], ah[mt][2], ah[mt][3], st + off);
                ldsm(al[mt][0], al[mt][1], al[mt][2], al[mt][3], st + 16384 + off);
            }
#pragma unroll
            for (int ng = 0; ng < 4; ++ng) {
                uint32_t boff = SWZ((wn * 64 + ng * 16 + ((lid >> 4) << 3) + (lid & 7)) * 128
                                    + kb + ((lid >> 3) & 1) * 16);
                uint32_t b0, b1, b2, b3;
                ldsm(b0, b1, b2, b3, st + 32768 + boff);
#pragma unroll
                for (int mt = 0; mt < 2; ++mt) {
                    mma16(acc[mt][ng * 2],     ah[mt][0], ah[mt][1], ah[mt][2], ah[mt][3], b0, b1);
                    mma16(acc[mt][ng * 2 + 1], ah[mt][0], ah[mt][1], ah[mt][2], ah[mt][3], b2, b3);
                    mma16(acc[mt][ng * 2],     al[mt][0], al[mt][1], al[mt][2], al[mt][3], b0, b1);
                    mma16(acc[mt][ng * 2 + 1], al[mt][0], al[mt][1], al[mt][2], al[mt][3], b2, b3);
                }
            }
        }
        __syncthreads();
    }

#pragma unroll
    for (int mt = 0; mt < 2; ++mt)
#pragma unroll
        for (int j = 0; j < 8; ++j) {
            int row = m0 + wm * 32 + mt * 16 + (lid >> 2);
            int col = n0 + wn * 64 + j * 8 + ((lid & 3) << 1);
            if (mode == 3) {
                *(float2*)(outp + (size_t)row * D_MODEL + col)       = make_float2(acc[mt][j][0], acc[mt][j][1]);
                *(float2*)(outp + (size_t)(row + 8) * D_MODEL + col) = make_float2(acc[mt][j][2], acc[mt][j][3]);
            } else {
                __half* dst = (mode == 0) ? g_Qh : (mode == 1) ? g_Kh : g_Vh;
                int h = col >> 6, d = col & 63;
                int b0_ = row >> 11, s0 = row & 2047, r1 = row + 8, b1_ = r1 >> 11, s1 = r1 & 2047;
                *(__half2*)(dst + (((size_t)(b0_ * NHEAD + h) * SEQ + s0)) * DH + d)
                    = __floats2half2_rn(acc[mt][j][0], acc[mt][j][1]);
                *(__half2*)(dst + (((size_t)(b1_ * NHEAD + h) * SEQ + s1)) * DH + d)
                    = __floats2half2_rn(acc[mt][j][2], acc[mt][j][3]);
            }
        }
}

// ---------------- fp16 tensor-core flash attention ----------------
// grid (16, 64): 128 queries/block, 8 warps x 16q. K/V tiles 64x64 double-buffered.
#define ATT_SMEM 49152   // Q 16K | K0 8K | V0 8K | K1 8K | V1 8K
__global__ __launch_bounds__(256) void attn_h()
{
    extern __shared__ char smem[];
    uint32_t sb = smem_u32(smem);
    uint32_t Qs = sb;
    uint32_t Ks[2] = {sb + 16384, sb + 32768};
    uint32_t Vs[2] = {sb + 24576, sb + 40960};

    int tid = threadIdx.x, lid = tid & 31, w = tid >> 5;
    int qb = (int)gridDim.x - 1 - (int)blockIdx.x;   // long blocks first
    int bh = blockIdx.y;

    const char* Qg = (const char*)(g_Qh + ((size_t)bh * SEQ + qb * 128) * DH);
    const char* Kg = (const char*)(g_Kh + (size_t)bh * SEQ * DH);
    const char* Vg = (const char*)(g_Vh + (size_t)bh * SEQ * DH);

    auto loadKV = [&](int kt, int buf) {
#pragma unroll
        for (int t = 0; t < 2; ++t) {
            int idx = tid + t * 256, row = idx >> 3, c = (idx & 7) * 16;
            uint32_t so = SWZ(row * 128 + c);
            cp16(Ks[buf] + so, Kg + (size_t)(kt * 64 + row) * 128 + c);
            cp16(Vs[buf] + so, Vg + (size_t)(kt * 64 + row) * 128 + c);
        }
    };

#pragma unroll
    for (int t = 0; t < 4; ++t) {
        int idx = tid + t * 256, row = idx >> 3, c = (idx & 7) * 16;
        cp16(Qs + SWZ(row * 128 + c), Qg + (size_t)row * 128 + c);
    }
    CP_COMMIT();
    loadKV(0, 0); CP_COMMIT();
    CP_WAIT(0); __syncthreads();

    uint32_t qf[4][4];
#pragma unroll
    for (int ks = 0; ks < 4; ++ks) {
        uint32_t off = SWZ((w * 16 + (lid & 15)) * 128 + ks * 32 + (lid >> 4) * 16);
        ldsm(qf[ks][0], qf[ks][1], qf[ks][2], qf[ks][3], Qs + off);
    }

    float o[8][4];
#pragma unroll
    for (int j = 0; j < 8; ++j)
#pragma unroll
        for (int v = 0; v < 4; ++v) o[j][v] = 0.f;
    float m0 = -1e30f, m1 = -1e30f, l0 = 0.f, l1 = 0.f;

    int r0 = lid >> 2, c0 = (lid & 3) << 1;
    int qlo = qb * 128 + w * 16;
    int ntiles = 2 * qb + 2;

    for (int kt = 0; kt < ntiles; ++kt) {
        int buf = kt & 1;
        if (kt + 1 < ntiles) { loadKV(kt + 1, buf ^ 1); CP_COMMIT(); CP_WAIT(1); }
        else CP_WAIT(0);
        __syncthreads();

        if (kt * 64 <= qlo + 15) {
            float s[8][4];
#pragma unroll
            for (int j = 0; j < 8; ++j)
#pragma unroll
                for (int v = 0; v < 4; ++v) s[j][v] = 0.f;
#pragma unroll
            for (int ks = 0; ks < 4; ++ks) {
                int kb = ks * 32;
#pragma unroll
                for (int ng = 0; ng < 4; ++ng) {
                    uint32_t boff = SWZ((ng * 16 + ((lid >> 4) << 3) + (lid & 7)) * 128
                                        + kb + ((lid >> 3) & 1) * 16);
                    uint32_t b0, b1, b2, b3;
                    ldsm(b0, b1, b2, b3, Ks[buf] + boff);
                    mma16(s[ng * 2],     qf[ks][0], qf[ks][1], qf[ks][2], qf[ks][3], b0, b1);
                    mma16(s[ng * 2 + 1], qf[ks][0], qf[ks][1], qf[ks][2], qf[ks][3], b2, b3);
                }
            }
            // scale + causal mask
            bool diag = (kt * 64 + 63 > qlo);
#pragma unroll
            for (int j = 0; j < 8; ++j)
#pragma unroll
                for (int v = 0; v < 4; ++v) {
                    float val = s[j][v] * 0.125f;
                    if (diag) {
                        int key = kt * 64 + j * 8 + c0 + (v & 1);
                        int q = qlo + r0 + ((v >> 1) << 3);
                        if (key > q) val = -1e30f;
                    }
                    s[j][v] = val;
                }
            // online softmax
            float mt0 = -1e30f, mt1 = -1e30f;
#pragma unroll
            for (int j = 0; j < 8; ++j) {
                mt0 = fmaxf(mt0, fmaxf(s[j][0], s[j][1]));
                mt1 = fmaxf(mt1, fmaxf(s[j][2], s[j][3]));
            }
            mt0 = fmaxf(mt0, __shfl_xor_sync(0xffffffffu, mt0, 1));
            mt0 = fmaxf(mt0, __shfl_xor_sync(0xffffffffu, mt0, 2));
            mt1 = fmaxf(mt1, __shfl_xor_sync(0xffffffffu, mt1, 1));
            mt1 = fmaxf(mt1, __shfl_xor_sync(0xffffffffu, mt1, 2));
            float mn0 = fmaxf(m0, mt0), mn1 = fmaxf(m1, mt1);
            float a0 = __expf(m0 - mn0), a1 = __expf(m1 - mn1);
            m0 = mn0; m1 = mn1;
            float ls0 = 0.f, ls1 = 0.f;
            uint32_t pa[8], pb[8];
#pragma unroll
            for (int j = 0; j < 8; ++j) {
                float p00 = __expf(s[j][0] - mn0), p01 = __expf(s[j][1] - mn0);
                float p10 = __expf(s[j][2] - mn1), p11 = __expf(s[j][3] - mn1);
                ls0 += p00 + p01; ls1 += p10 + p11;
                pa[j] = packh2(p00, p01);
                pb[j] = packh2(p10, p11);
            }
            ls0 += __shfl_xor_sync(0xffffffffu, ls0, 1);
            ls0 += __shfl_xor_sync(0xffffffffu, ls0, 2);
            ls1 += __shfl_xor_sync(0xffffffffu, ls1, 1);
            ls1 += __shfl_xor_sync(0xffffffffu, ls1, 2);
            l0 = l0 * a0 + ls0; l1 = l1 * a1 + ls1;
#pragma unroll
            for (int j = 0; j < 8; ++j) {
                o[j][0] *= a0; o[j][1] *= a0; o[j][2] *= a1; o[j][3] *= a1;
            }
            // O += P * V  (V via ldmatrix.trans)
#pragma unroll
            for (int ks2 = 0; ks2 < 4; ++ks2) {
                uint32_t A0 = pa[2 * ks2], A1 = pb[2 * ks2], A2 = pa[2 * ks2 + 1], A3 = pb[2 * ks2 + 1];
#pragma unroll
                for (int ng = 0; ng < 4; ++ng) {
                    uint32_t voff = SWZ((ks2 * 16 + ((lid >> 3) & 1) * 8 + (lid & 7)) * 128
                                        + ng * 32 + (lid >> 4) * 16);
                    uint32_t b0, b1, b2, b3;
                    ldsmT(b0, b1, b2, b3, Vs[buf] + voff);
                    mma16(o[ng * 2],     A0, A1, A2, A3, b0, b1);
                    mma16(o[ng * 2 + 1], A0, A1, A2, A3, b2, b3);
                }
            }
        }
        __syncthreads();
    }

    // epilogue -> g_Te hi|lo
    float il0 = 1.f / l0, il1 = 1.f / l1;
    int b = bh >> 4, h = bh & 15;
    size_t t0 = (size_t)b * SEQ + qb * 128 + w * 16 + r0;
    size_t t1 = t0 + 8;
#pragma unroll
    for (int j = 0; j < 8; ++j) {
        int d = h * 64 + j * 8 + c0;
        float x0 = o[j][0] * il0, x1 = o[j][1] * il0;
        float y0 = o[j][2] * il1, y1 = o[j][3] * il1;
        __half h0 = __float2half_rn(x0), h1 = __float2half_rn(x1);
        __half g0 = __float2half_rn(y0), g1 = __float2half_rn(y1);
        *(__half2*)&g_Te[t0 * KE + d] = __halves2half2(h0, h1);
        *(__half2*)&g_Te[t1 * KE + d] = __halves2half2(g0, g1);
        *(__half2*)&g_Te[t0 * KE + 1024 + d] =
            __floats2half2_rn(x0 - __half2float(h0), x1 - __half2float(h1));
        *(__half2*)&g_Te[t1 * KE + 1024 + d] =
            __floats2half2_rn(y0 - __half2float(g0), y1 - __half2float(g1));
    }
}

// ---------------- launch ----------------
extern "C" void kernel_launch(void* const* d_in, const int* in_sizes, int n_in,
                              void* d_out, int out_size)
{
    const float* X  = (const float*)d_in[0];
    const float* WQ = (const float*)d_in[1];
    const float* WK = (const float*)d_in[2];
    const float* WV = (const float*)d_in[3];
    const float* WO = (const float*)d_in[4];
    float* out = (float*)d_out;

    conv_x<<<2048, 256>>>(X);
    conv_w<<<512, 256>>>(WQ, 0);
    conv_w<<<512, 256>>>(WK, 1);
    conv_w<<<512, 256>>>(WV, 2);
    conv_w<<<512, 256>>>(WO, 3);

    cudaFuncSetAttribute(gemm_h, cudaFuncAttributeMaxDynamicSharedMemorySize, 2 * GST);
    cudaFuncSetAttribute(attn_h, cudaFuncAttributeMaxDynamicSharedMemorySize, ATT_SMEM);

    dim3 gg(D_MODEL / 128, MTOT / 128);      // (8, 64)
    gemm_h<<<gg, 256, 2 * GST>>>(nullptr, 0);   // Q
    gemm_h<<<gg, 256, 2 * GST>>>(nullptr, 1);   // K
    gemm_h<<<gg, 256, 2 * GST>>>(nullptr, 2);   // V

    dim3 ag(SEQ / 128, BATCH * NHEAD);       // (16, 64)
    attn_h<<<ag, 256, ATT_SMEM>>>();

    gemm_h<<<gg, 256, 2 * GST>>>(out, 3);       // output projection
}

// round 10
// speedup vs baseline: 5.1974x; 1.1065x over previous
#include <cuda_runtime.h>
#include <cuda_fp16.h>
#include <stdint.h>

#define D_MODEL 1024
#define NHEAD   16
#define DH      64
#define SEQ     2048
#define BATCH   4
#define MTOT    8192
#define KE      2048

// ---------------- scratch globals (no allocation) ----------------
__device__ __half g_Xe[(size_t)MTOT*KE];                 // X hi|lo
__device__ __half g_Te[(size_t)MTOT*KE];                 // attn out hi|lo
__device__ __half g_W[4][(size_t)D_MODEL*D_MODEL];       // weights fp16
__device__ __half g_Qh[(size_t)BATCH*NHEAD*SEQ*DH];      // [B,H,S,64]
__device__ __half g_Kh[(size_t)BATCH*NHEAD*SEQ*DH];
__device__ __half g_Vh[(size_t)BATCH*NHEAD*SEQ*DH];

// ---------------- helpers ----------------
__device__ __forceinline__ uint32_t smem_u32(const void* p) {
    uint32_t a;
    asm("{ .reg .u64 t; cvta.to.shared.u64 t, %1; cvt.u32.u64 %0, t; }" : "=r"(a) : "l"(p));
    return a;
}
__device__ __forceinline__ void cp16(uint32_t s, const void* g) {
    asm volatile("cp.async.cg.shared.global [%0], [%1], 16;" :: "r"(s), "l"(g));
}
#define CP_COMMIT() asm volatile("cp.async.commit_group;" ::: "memory")
#define CP_WAIT(n)  asm volatile("cp.async.wait_group %0;" :: "n"(n) : "memory")

__device__ __forceinline__ void ldsm(uint32_t& r0, uint32_t& r1, uint32_t& r2, uint32_t& r3, uint32_t a) {
    asm volatile("ldmatrix.sync.aligned.m8n8.x4.shared.b16 {%0,%1,%2,%3}, [%4];"
                 : "=r"(r0), "=r"(r1), "=r"(r2), "=r"(r3) : "r"(a));
}
__device__ __forceinline__ void ldsmT(uint32_t& r0, uint32_t& r1, uint32_t& r2, uint32_t& r3, uint32_t a) {
    asm volatile("ldmatrix.sync.aligned.m8n8.x4.trans.shared.b16 {%0,%1,%2,%3}, [%4];"
                 : "=r"(r0), "=r"(r1), "=r"(r2), "=r"(r3) : "r"(a));
}
__device__ __forceinline__ void mma16(float* c, uint32_t a0, uint32_t a1, uint32_t a2, uint32_t a3,
                                      uint32_t b0, uint32_t b1) {
    asm volatile("mma.sync.aligned.m16n8k16.row.col.f32.f16.f16.f32 "
                 "{%0,%1,%2,%3}, {%4,%5,%6,%7}, {%8,%9}, {%0,%1,%2,%3};"
                 : "+f"(c[0]), "+f"(c[1]), "+f"(c[2]), "+f"(c[3])
                 : "r"(a0), "r"(a1), "r"(a2), "r"(a3), "r"(b0), "r"(b1));
}
#define SWZ(x) ((uint32_t)(x) ^ ((((uint32_t)(x)) >> 3) & 0x70))

__device__ __forceinline__ uint32_t packh2(float a, float b) {
    __half2 h = __floats2half2_rn(a, b);
    return *reinterpret_cast<uint32_t*>(&h);
}

// ---------------- converters ----------------
__global__ void conv_x(const float* __restrict__ s) {
    for (int i = blockIdx.x * blockDim.x + threadIdx.x; i < MTOT * D_MODEL; i += gridDim.x * blockDim.x) {
        int r = i >> 10, c = i & 1023;
        float x = s[i];
        __half h = __float2half_rn(x);
        g_Xe[(size_t)r * KE + c]        = h;
        g_Xe[(size_t)r * KE + 1024 + c] = __float2half_rn(x - __half2float(h));
    }
}
__global__ void conv_w4(const float* __restrict__ w0, const float* __restrict__ w1,
                        const float* __restrict__ w2, const float* __restrict__ w3) {
    const int N = D_MODEL * D_MODEL;
    for (int i = blockIdx.x * blockDim.x + threadIdx.x; i < 4 * N; i += gridDim.x * blockDim.x) {
        int m = i >> 20, idx = i & (N - 1);
        const float* s = (m == 0) ? w0 : (m == 1) ? w1 : (m == 2) ? w2 : w3;
        g_W[m][idx] = __float2half_rn(s[idx]);
    }
}

// ---------------- 2-pass fp16 GEMM: C = (Ah+Al) * W^T ----------------
// 128x128 block tile, 4 warps (2x2) of 64x64; 16 K-chunks of 64.
// stage = Ah(16K)|Al(16K)|B(16K) = 48KB, double buffered -> 2 CTAs/SM.
#define GST 49152
__global__ __launch_bounds__(128) void gemm_h(float* __restrict__ outp, int mode)
{
    extern __shared__ char smem[];
    uint32_t sb = smem_u32(smem);
    int tid = threadIdx.x, lid = tid & 31, wid = tid >> 5;
    int wm = wid >> 1, wn = wid & 1;
    int m0 = blockIdx.y * 128, n0 = blockIdx.x * 128;

    const __half* A = (mode == 3) ? g_Te : g_Xe;
    const char* Ab = (const char*)(A + (size_t)m0 * KE);
    const char* Bb = (const char*)(g_W[mode] + (size_t)n0 * D_MODEL);

    float acc[4][8][4];
#pragma unroll
    for (int mt = 0; mt < 4; ++mt)
#pragma unroll
        for (int j = 0; j < 8; ++j)
#pragma unroll
            for (int v = 0; v < 4; ++v) acc[mt][j][v] = 0.f;

    auto LD = [&](int c, uint32_t st) {
#pragma unroll
        for (int t = 0; t < 8; ++t) {
            int idx = tid + t * 128, row = idx >> 3, cc = (idx & 7) * 16;
            uint32_t so = SWZ(row * 128 + cc);
            cp16(st + so,         Ab + (size_t)row * 4096 + c * 128 + cc);
            cp16(st + 16384 + so, Ab + (size_t)row * 4096 + 2048 + c * 128 + cc);
            cp16(st + 32768 + so, Bb + (size_t)row * 2048 + c * 128 + cc);
        }
    };

    LD(0, sb); CP_COMMIT();
    for (int i = 0; i < 16; ++i) {
        int cur = i & 1;
        if (i + 1 < 16) { LD(i + 1, sb + (cur ^ 1) * GST); CP_COMMIT(); CP_WAIT(1); }
        else CP_WAIT(0);
        __syncthreads();
        uint32_t st = sb + cur * GST;
#pragma unroll
        for (int ks = 0; ks < 4; ++ks) {
            int kb = ks * 32;
            uint32_t ah[4][4], al[4][4];
#pragma unroll
            for (int mt = 0; mt < 4; ++mt) {
                uint32_t off = SWZ((wm * 64 + mt * 16 + (lid & 15)) * 128 + kb + (lid >> 4) * 16);
                ldsm(ah[mt][0], ah[mt][1], ah[mt][2], ah[mt][3], st + off);
                ldsm(al[mt][0], al[mt][1], al[mt][2], al[mt][3], st + 16384 + off);
            }
#pragma unroll
            for (int ng = 0; ng < 4; ++ng) {
                uint32_t boff = SWZ((wn * 64 + ng * 16 + ((lid >> 4) << 3) + (lid & 7)) * 128
                                    + kb + ((lid >> 3) & 1) * 16);
                uint32_t b0, b1, b2, b3;
                ldsm(b0, b1, b2, b3, st + 32768 + boff);
#pragma unroll
                for (int mt = 0; mt < 4; ++mt) {
                    mma16(acc[mt][ng * 2],     ah[mt][0], ah[mt][1], ah[mt][2], ah[mt][3], b0, b1);
                    mma16(acc[mt][ng * 2 + 1], ah[mt][0], ah[mt][1], ah[mt][2], ah[mt][3], b2, b3);
                    mma16(acc[mt][ng * 2],     al[mt][0], al[mt][1], al[mt][2], al[mt][3], b0, b1);
                    mma16(acc[mt][ng * 2 + 1], al[mt][0], al[mt][1], al[mt][2], al[mt][3], b2, b3);
                }
            }
        }
        __syncthreads();
    }

#pragma unroll
    for (int mt = 0; mt < 4; ++mt)
#pragma unroll
        for (int j = 0; j < 8; ++j) {
            int row = m0 + wm * 64 + mt * 16 + (lid >> 2);
            int col = n0 + wn * 64 + j * 8 + ((lid & 3) << 1);
            if (mode == 3) {
                *(float2*)(outp + (size_t)row * D_MODEL + col)       = make_float2(acc[mt][j][0], acc[mt][j][1]);
                *(float2*)(outp + (size_t)(row + 8) * D_MODEL + col) = make_float2(acc[mt][j][2], acc[mt][j][3]);
            } else {
                __half* dst = (mode == 0) ? g_Qh : (mode == 1) ? g_Kh : g_Vh;
                int h = col >> 6, d = col & 63;
                int b0_ = row >> 11, s0 = row & 2047, r1 = row + 8, b1_ = r1 >> 11, s1 = r1 & 2047;
                *(__half2*)(dst + (((size_t)(b0_ * NHEAD + h) * SEQ + s0)) * DH + d)
                    = __floats2half2_rn(acc[mt][j][0], acc[mt][j][1]);
                *(__half2*)(dst + (((size_t)(b1_ * NHEAD + h) * SEQ + s1)) * DH + d)
                    = __floats2half2_rn(acc[mt][j][2], acc[mt][j][3]);
            }
        }
}

// ---------------- fp16 tensor-core flash attention (unchanged, known-good) ----------------
#define ATT_SMEM 49152   // Q 16K | K0 8K | V0 8K | K1 8K | V1 8K
__global__ __launch_bounds__(256) void attn_h()
{
    extern __shared__ char smem[];
    uint32_t sb = smem_u32(smem);
    uint32_t Qs = sb;
    uint32_t Ks[2] = {sb + 16384, sb + 32768};
    uint32_t Vs[2] = {sb + 24576, sb + 40960};

    int tid = threadIdx.x, lid = tid & 31, w = tid >> 5;
    int qb = (int)gridDim.x - 1 - (int)blockIdx.x;
    int bh = blockIdx.y;

    const char* Qg = (const char*)(g_Qh + ((size_t)bh * SEQ + qb * 128) * DH);
    const char* Kg = (const char*)(g_Kh + (size_t)bh * SEQ * DH);
    const char* Vg = (const char*)(g_Vh + (size_t)bh * SEQ * DH);

    auto loadKV = [&](int kt, int buf) {
#pragma unroll
        for (int t = 0; t < 2; ++t) {
            int idx = tid + t * 256, row = idx >> 3, c = (idx & 7) * 16;
            uint32_t so = SWZ(row * 128 + c);
            cp16(Ks[buf] + so, Kg + (size_t)(kt * 64 + row) * 128 + c);
            cp16(Vs[buf] + so, Vg + (size_t)(kt * 64 + row) * 128 + c);
        }
    };

#pragma unroll
    for (int t = 0; t < 4; ++t) {
        int idx = tid + t * 256, row = idx >> 3, c = (idx & 7) * 16;
        cp16(Qs + SWZ(row * 128 + c), Qg + (size_t)row * 128 + c);
    }
    CP_COMMIT();
    loadKV(0, 0); CP_COMMIT();
    CP_WAIT(0); __syncthreads();

    uint32_t qf[4][4];
#pragma unroll
    for (int ks = 0; ks < 4; ++ks) {
        uint32_t off = SWZ((w * 16 + (lid & 15)) * 128 + ks * 32 + (lid >> 4) * 16);
        ldsm(qf[ks][0], qf[ks][1], qf[ks][2], qf[ks][3], Qs + off);
    }

    float o[8][4];
#pragma unroll
    for (int j = 0; j < 8; ++j)
#pragma unroll
        for (int v = 0; v < 4; ++v) o[j][v] = 0.f;
    float m0 = -1e30f, m1 = -1e30f, l0 = 0.f, l1 = 0.f;

    int r0 = lid >> 2, c0 = (lid & 3) << 1;
    int qlo = qb * 128 + w * 16;
    int ntiles = 2 * qb + 2;

    for (int kt = 0; kt < ntiles; ++kt) {
        int buf = kt & 1;
        if (kt + 1 < ntiles) { loadKV(kt + 1, buf ^ 1); CP_COMMIT(); CP_WAIT(1); }
        else CP_WAIT(0);
        __syncthreads();

        if (kt * 64 <= qlo + 15) {
            float s[8][4];
#pragma unroll
            for (int j = 0; j < 8; ++j)
#pragma unroll
                for (int v = 0; v < 4; ++v) s[j][v] = 0.f;
#pragma unroll
            for (int ks = 0; ks < 4; ++ks) {
                int kb = ks * 32;
#pragma unroll
                for (int ng = 0; ng < 4; ++ng) {
                    uint32_t boff = SWZ((ng * 16 + ((lid >> 4) << 3) + (lid & 7)) * 128
                                        + kb + ((lid >> 3) & 1) * 16);
                    uint32_t b0, b1, b2, b3;
                    ldsm(b0, b1, b2, b3, Ks[buf] + boff);
                    mma16(s[ng * 2],     qf[ks][0], qf[ks][1], qf[ks][2], qf[ks][3], b0, b1);
                    mma16(s[ng * 2 + 1], qf[ks][0], qf[ks][1], qf[ks][2], qf[ks][3], b2, b3);
                }
            }
            bool diag = (kt * 64 + 63 > qlo);
#pragma unroll
            for (int j = 0; j < 8; ++j)
#pragma unroll
                for (int v = 0; v < 4; ++v) {
                    float val = s[j][v] * 0.125f;
                    if (diag) {
                        int key = kt * 64 + j * 8 + c0 + (v & 1);
                        int q = qlo + r0 + ((v >> 1) << 3);
                        if (key > q) val = -1e30f;
                    }
                    s[j][v] = val;
                }
            float mt0 = -1e30f, mt1 = -1e30f;
#pragma unroll
            for (int j = 0; j < 8; ++j) {
                mt0 = fmaxf(mt0, fmaxf(s[j][0], s[j][1]));
                mt1 = fmaxf(mt1, fmaxf(s[j][2], s[j][3]));
            }
            mt0 = fmaxf(mt0, __shfl_xor_sync(0xffffffffu, mt0, 1));
            mt0 = fmaxf(mt0, __shfl_xor_sync(0xffffffffu, mt0, 2));
            mt1 = fmaxf(mt1, __shfl_xor_sync(0xffffffffu, mt1, 1));
            mt1 = fmaxf(mt1, __shfl_xor_sync(0xffffffffu, mt1, 2));
            float mn0 = fmaxf(m0, mt0), mn1 = fmaxf(m1, mt1);
            float a0 = __expf(m0 - mn0), a1 = __expf(m1 - mn1);
            m0 = mn0; m1 = mn1;
            float ls0 = 0.f, ls1 = 0.f;
            uint32_t pa[8], pb[8];
#pragma unroll
            for (int j = 0; j < 8; ++j) {
                float p00 = __expf(s[j][0] - mn0), p01 = __expf(s[j][1] - mn0);
                float p10 = __expf(s[j][2] - mn1), p11 = __expf(s[j][3] - mn1);
                ls0 += p00 + p01; ls1 += p10 + p11;
                pa[j] = packh2(p00, p01);
                pb[j] = packh2(p10, p11);
            }
            ls0 += __shfl_xor_sync(0xffffffffu, ls0, 1);
            ls0 += __shfl_xor_sync(0xffffffffu, ls0, 2);
            ls1 += __shfl_xor_sync(0xffffffffu, ls1, 1);
            ls1 += __shfl_xor_sync(0xffffffffu, ls1, 2);
            l0 = l0 * a0 + ls0; l1 = l1 * a1 + ls1;
#pragma unroll
            for (int j = 0; j < 8; ++j) {
                o[j][0] *= a0; o[j][1] *= a0; o[j][2] *= a1; o[j][3] *= a1;
            }
#pragma unroll
            for (int ks2 = 0; ks2 < 4; ++ks2) {
                uint32_t A0 = pa[2 * ks2], A1 = pb[2 * ks2], A2 = pa[2 * ks2 + 1], A3 = pb[2 * ks2 + 1];
#pragma unroll
                for (int ng = 0; ng < 4; ++ng) {
                    uint32_t voff = SWZ((ks2 * 16 + ((lid >> 3) & 1) * 8 + (lid & 7)) * 128
                                        + ng * 32 + (lid >> 4) * 16);
                    uint32_t b0, b1, b2, b3;
                    ldsmT(b0, b1, b2, b3, Vs[buf] + voff);
                    mma16(o[ng * 2],     A0, A1, A2, A3, b0, b1);
                    mma16(o[ng * 2 + 1], A0, A1, A2, A3, b2, b3);
                }
            }
        }
        __syncthreads();
    }

    float il0 = 1.f / l0, il1 = 1.f / l1;
    int b = bh >> 4, h = bh & 15;
    size_t t0 = (size_t)b * SEQ + qb * 128 + w * 16 + r0;
    size_t t1 = t0 + 8;
#pragma unroll
    for (int j = 0; j < 8; ++j) {
        int d = h * 64 + j * 8 + c0;
        float x0 = o[j][0] * il0, x1 = o[j][1] * il0;
        float y0 = o[j][2] * il1, y1 = o[j][3] * il1;
        __half h0 = __float2half_rn(x0), h1 = __float2half_rn(x1);
        __half g0 = __float2half_rn(y0), g1 = __float2half_rn(y1);
        *(__half2*)&g_Te[t0 * KE + d] = __halves2half2(h0, h1);
        *(__half2*)&g_Te[t1 * KE + d] = __halves2half2(g0, g1);
        *(__half2*)&g_Te[t0 * KE + 1024 + d] =
            __floats2half2_rn(x0 - __half2float(h0), x1 - __half2float(h1));
        *(__half2*)&g_Te[t1 * KE + 1024 + d] =
            __floats2half2_rn(y0 - __half2float(g0), y1 - __half2float(g1));
    }
}

// ---------------- launch ----------------
extern "C" void kernel_launch(void* const* d_in, const int* in_sizes, int n_in,
                              void* d_out, int out_size)
{
    const float* X  = (const float*)d_in[0];
    const float* WQ = (const float*)d_in[1];
    const float* WK = (const float*)d_in[2];
    const float* WV = (const float*)d_in[3];
    const float* WO = (const float*)d_in[4];
    float* out = (float*)d_out;

    conv_x<<<2048, 256>>>(X);
    conv_w4<<<2048, 256>>>(WQ, WK, WV, WO);

    cudaFuncSetAttribute(gemm_h, cudaFuncAttributeMaxDynamicSharedMemorySize, 2 * GST);
    cudaFuncSetAttribute(attn_h, cudaFuncAttributeMaxDynamicSharedMemorySize, ATT_SMEM);

    dim3 gg(D_MODEL / 128, MTOT / 128);      // (8, 64)
    gemm_h<<<gg, 128, 2 * GST>>>(nullptr, 0);   // Q
    gemm_h<<<gg, 128, 2 * GST>>>(nullptr, 1);   // K
    gemm_h<<<gg, 128, 2 * GST>>>(nullptr, 2);   // V

    dim3 ag(SEQ / 128, BATCH * NHEAD);       // (16, 64)
    attn_h<<<ag, 256, ATT_SMEM>>>();

    gemm_h<<<gg, 128, 2 * GST>>>(out, 3);       // output projection
}